// round 8
// baseline (speedup 1.0000x reference)
#include <cuda_runtime.h>
#include <cuda_fp16.h>
#include <math.h>
#include <stdint.h>

#define BSZ 512
#define INPD 512
#define CD 1024
#define ND 256
#define DD 128
#define HH 8

// ---------------- scratch (single device global, no allocations) ----------
#define GATES_OFF 0
#define HEADS_OFF 2097152
#define WW_OFF    4194304
#define BR_OFF    5242880
#define BW_OFF    5246976
#define SH_OFF    5251072
#define GA_OFF    5263360
#define SCRATCH_TOTAL 5267456

__device__ float g_scratch[SCRATCH_TOTAL];

__device__ __forceinline__ float sigf(float x){ return __fdividef(1.f, 1.f + __expf(-x)); }
__device__ __forceinline__ float tanhfast(float x){
    float e = __expf(2.f*x);
    return 1.f - __fdividef(2.f, e + 1.f);
}
__device__ __forceinline__ float softplusf_(float x){ return x>20.f ? x : log1pf(expf(x)); }

// =====================  fp16 tensor-core GEMM ================================
// C[M,N] = sum_seg A_seg[M,Kseg] @ W_seg[N,Kseg]^T + bias (+bias2)
// BM=128, BN=64, BK=32. 256 threads, 8 warps (4m x 2n), warp tile 32x32,
// mma m16n8k16, ldmatrix fragment loads, double-buffered smem, 2 CTAs/SM.

struct GemmSeg {
    const float* A; int lda;
    const float* W0; const float* W1; const float* W2; const float* W3; // N-quarters
    int ldw; int klen;
};
struct GemmCfg {
    GemmSeg s[3];
    int nseg; int S;
    const float* b0; const float* b1; const float* b2; const float* b3;
    const float* e0; const float* e1; const float* e2; const float* e3;
    int has2;
    float* C; int ldc;
};

// word (uint32 = 2 halves) position: row r, word w (0..15); XOR swizzle on
// 4-word (16B) chunks -> conflict-free STS.64 and ldmatrix phases.
__device__ __forceinline__ int swzw(int r, int w){
    return (r<<4) + (w ^ (((r>>1)&3)<<2));
}

__device__ __forceinline__ void stage_of(const GemmCfg& cfg, int s, int& seg, int& k0){
    int acc = 0;
    #pragma unroll
    for (int i=0;i<3;i++){
        if (i >= cfg.nseg) break;
        int ns = cfg.s[i].klen >> 5;
        if (s < acc + ns){ seg = i; k0 = (s - acc) << 5; return; }
        acc += ns;
    }
    seg = 0; k0 = 0;
}

__device__ __forceinline__ void ld_tiles(const GemmSeg& sg, int bm, int bn, int r, int c,
                                         int k0, float4* va, float4* vb)
{
    int q = bn>>10;
    const float* Wq = (q==0)?sg.W0:(q==1)?sg.W1:(q==2)?sg.W2:sg.W3;
    const float* Ab = sg.A + (size_t)(bm + r)*sg.lda + k0 + c*4;
    const float* Bb = Wq  + (size_t)((bn&1023) + r)*sg.ldw + k0 + c*4;
    #pragma unroll
    for (int j=0;j<4;j++) va[j] = *(const float4*)(Ab + (size_t)(32*j)*sg.lda);
    #pragma unroll
    for (int j=0;j<2;j++) vb[j] = *(const float4*)(Bb + (size_t)(32*j)*sg.ldw);
}

__device__ __forceinline__ uint2 pack_h4(float4 v){
    __half2 lo = __floats2half2_rn(v.x, v.y);
    __half2 hi = __floats2half2_rn(v.z, v.w);
    uint2 u;
    u.x = *(uint32_t*)&lo;
    u.y = *(uint32_t*)&hi;
    return u;
}

__device__ __forceinline__ void st_stage(uint32_t* Asb, uint32_t* Bsb, int r, int c,
                                         const float4* va, const float4* vb)
{
    #pragma unroll
    for (int j=0;j<4;j++)
        *(uint2*)&Asb[swzw(r + 32*j, 2*c)] = pack_h4(va[j]);
    #pragma unroll
    for (int j=0;j<2;j++)
        *(uint2*)&Bsb[swzw(r + 32*j, 2*c)] = pack_h4(vb[j]);
}

__device__ __forceinline__ void ldm_x4(uint32_t& r0, uint32_t& r1, uint32_t& r2, uint32_t& r3,
                                       uint32_t addr){
    asm volatile("ldmatrix.sync.aligned.m8n8.x4.shared.b16 {%0,%1,%2,%3}, [%4];"
        : "=r"(r0), "=r"(r1), "=r"(r2), "=r"(r3) : "r"(addr));
}

__global__ void __launch_bounds__(256,2) gemm_f16(GemmCfg cfg)
{
    __shared__ __align__(16) uint32_t As[2][2048];  // 128 rows x 16 words
    __shared__ __align__(16) uint32_t Bs[2][1024];  //  64 rows x 16 words
    const int tid = threadIdx.x;
    const int wid = tid>>5, lane = tid&31;
    const int bm = blockIdx.y*128, bn = blockIdx.x*64;
    const int wm = (wid>>1)*32, wn = (wid&1)*32;
    const int g = lane>>2, tig = lane&3;
    const int grp = lane>>3, rowin = lane&7;
    const int r = tid >> 3;          // loader row (0..31), +32*j
    const int c = tid & 7;           // loader float4 chunk (0..7)

    const uint32_t smA = (uint32_t)__cvta_generic_to_shared(&As[0][0]);
    const uint32_t smB = (uint32_t)__cvta_generic_to_shared(&Bs[0][0]);

    float acc[2][4][4];
    #pragma unroll
    for (int i=0;i<2;i++)
        #pragma unroll
        for (int j=0;j<4;j++)
            #pragma unroll
            for (int t=0;t<4;t++) acc[i][j][t]=0.f;

    float4 va[4], vb[2];
    int seg, k0;

    stage_of(cfg, 0, seg, k0);
    ld_tiles(cfg.s[seg], bm,bn,r,c, k0, va,vb);
    st_stage(As[0], Bs[0], r, c, va, vb);
    __syncthreads();

    if (cfg.S > 1){
        stage_of(cfg, 1, seg, k0);
        ld_tiles(cfg.s[seg], bm,bn,r,c, k0, va,vb);
    }

    for (int s = 0; s < cfg.S; s++){
        const int buf = s & 1;
        const uint32_t aBase = smA + buf*2048*4;
        const uint32_t bBase = smB + buf*1024*4;

        #pragma unroll
        for (int kk=0;kk<2;kk++){
            const int kb = kk*8;   // word offset (8 words = 16 k halves)
            uint32_t af[2][4], bf[2][4];
            // A fragments: matrices [m0 k0, m0+8 k0, m0 k8, m0+8 k8]
            #pragma unroll
            for (int mf=0;mf<2;mf++){
                int arow  = wm + mf*16 + ((grp&1)<<3) + rowin;
                int aword = kb + ((grp>>1)<<2);
                uint32_t aw = (arow<<4) + (aword ^ (((arow>>1)&3)<<2));
                ldm_x4(af[mf][0], af[mf][1], af[mf][2], af[mf][3], aBase + 4*aw);
            }
            // B fragments (pair of 8-wide n tiles): [n0 k0, n0 k8, n0+8 k0, n0+8 k8]
            #pragma unroll
            for (int nf2=0;nf2<2;nf2++){
                int brow  = wn + nf2*16 + ((grp>>1)<<3) + rowin;
                int bword = kb + ((grp&1)<<2);
                uint32_t bw = (brow<<4) + (bword ^ (((brow>>1)&3)<<2));
                ldm_x4(bf[nf2][0], bf[nf2][1], bf[nf2][2], bf[nf2][3], bBase + 4*bw);
            }
            #pragma unroll
            for (int mf=0;mf<2;mf++)
                #pragma unroll
                for (int nf=0;nf<4;nf++)
                    asm volatile(
                        "mma.sync.aligned.m16n8k16.row.col.f32.f16.f16.f32 "
                        "{%0,%1,%2,%3},{%4,%5,%6,%7},{%8,%9},{%0,%1,%2,%3};"
                        : "+f"(acc[mf][nf][0]), "+f"(acc[mf][nf][1]),
                          "+f"(acc[mf][nf][2]), "+f"(acc[mf][nf][3])
                        : "r"(af[mf][0]), "r"(af[mf][1]), "r"(af[mf][2]), "r"(af[mf][3]),
                          "r"(bf[nf>>1][(nf&1)*2]), "r"(bf[nf>>1][(nf&1)*2+1]));
        }

        if (s+1 < cfg.S){
            st_stage(As[buf^1], Bs[buf^1], r, c, va, vb);
            __syncthreads();
            if (s+2 < cfg.S){
                stage_of(cfg, s+2, seg, k0);
                ld_tiles(cfg.s[seg], bm,bn,r,c, k0, va,vb);
            }
        }
    }

    // epilogue
    const int q = bn>>10;
    const float* bq = (q==0)?cfg.b0:(q==1)?cfg.b1:(q==2)?cfg.b2:cfg.b3;
    const float* eq = (q==0)?cfg.e0:(q==1)?cfg.e1:(q==2)?cfg.e2:cfg.e3;
    #pragma unroll
    for (int mf=0;mf<2;mf++){
        int row = bm + wm + mf*16 + g;
        #pragma unroll
        for (int nf=0;nf<4;nf++){
            int col = bn + wn + nf*8 + 2*tig;
            int cq = col & 1023;
            float b0v = bq[cq], b1v = bq[cq+1];
            if (cfg.has2){ b0v += eq[cq]; b1v += eq[cq+1]; }
            float2 v0; v0.x = acc[mf][nf][0] + b0v; v0.y = acc[mf][nf][1] + b1v;
            float2 v1; v1.x = acc[mf][nf][2] + b0v; v1.y = acc[mf][nf][3] + b1v;
            *(float2*)&cfg.C[(size_t)row*cfg.ldc + col]     = v0;
            *(float2*)&cfg.C[(size_t)(row+8)*cfg.ldc + col] = v1;
        }
    }
}

// ---------------- LSTM pointwise (gate order i,f,g,o) ----------------------
__global__ void lstm_pw(const float* __restrict__ g, const float* __restrict__ cprev,
                        float* __restrict__ hout, float* __restrict__ cout)
{
    int idx = blockIdx.x*blockDim.x + threadIdx.x;
    if (idx >= BSZ*CD) return;
    int bb = idx >> 10, cc = idx & 1023;
    const float* gr = g + (size_t)bb*4096;
    float gi = sigf(gr[cc]);
    float gf = sigf(gr[1024+cc]);
    float gg = tanhfast(gr[2048+cc]);
    float go = sigf(gr[3072+cc]);
    float cn = gf*cprev[idx] + gi*gg;
    cout[idx] = cn;
    hout[idx] = go * tanhfast(cn);
}

// ---------------- fused small heads -----------------------------------------
__global__ void gemv_heads4(const float* __restrict__ h,
                            const float* __restrict__ Wrb, const float* __restrict__ brb,
                            const float* __restrict__ Wwb, const float* __restrict__ bwb,
                            const float* __restrict__ Wsh, const float* __restrict__ bsh,
                            const float* __restrict__ Wga, const float* __restrict__ bga,
                            float* __restrict__ orb, float* __restrict__ owb,
                            float* __restrict__ osh, float* __restrict__ oga)
{
    int gw = (blockIdx.x*blockDim.x + threadIdx.x) >> 5;
    int lane = threadIdx.x & 31;
    if (gw >= BSZ*48) return;
    int bidx = gw / 48, t = gw - bidx*48;
    const float* W; const float* bias; float* out; int n; int nout;
    if (t < 8)       { W=Wrb; bias=brb; out=orb; n=t;     nout=8;  }
    else if (t < 16) { W=Wwb; bias=bwb; out=owb; n=t-8;   nout=8;  }
    else if (t < 40) { W=Wsh; bias=bsh; out=osh; n=t-16;  nout=24; }
    else             { W=Wga; bias=bga; out=oga; n=t-40;  nout=8;  }
    const float4* hv = (const float4*)(h + (size_t)bidx*CD);
    const float4* wv = (const float4*)(W + (size_t)n*CD);
    float s = 0.f;
    #pragma unroll 4
    for (int i=lane; i<CD/4; i+=32){
        float4 a=hv[i], w=wv[i];
        s += a.x*w.x + a.y*w.y + a.z*w.z + a.w*w.w;
    }
    #pragma unroll
    for (int o=16;o;o>>=1) s += __shfl_xor_sync(0xffffffffu, s, o);
    if (lane==0) out[(size_t)bidx*nout + n] = s + bias[n];
}

// ---------------- content addressing (write path) --------------------------
__global__ void __launch_bounds__(256) content_w(
    const float* __restrict__ Mm,
    const float* __restrict__ Kraw, int ldk,
    const float* __restrict__ braw,
    float* __restrict__ wout)
{
    int b = blockIdx.x;
    __shared__ __align__(16) float Kn[HH][DD];
    __shared__ float cosm[HH][ND];
    __shared__ float inv[HH];
    int tid = threadIdx.x, wid = tid>>5, lane = tid&31;

    for (int i=tid; i<HH*DD; i+=256) Kn[i>>7][i&127] = Kraw[(size_t)b*ldk + i];
    __syncthreads();
    {
        float s=0.f;
        for (int d=lane; d<DD; d+=32){ float v=Kn[wid][d]; s+=v*v; }
        #pragma unroll
        for (int o=16;o;o>>=1) s += __shfl_xor_sync(0xffffffffu, s, o);
        if (lane==0) inv[wid] = 1.f / fmaxf(sqrtf(s), 1e-12f);
    }
    __syncthreads();
    for (int i=tid; i<HH*DD; i+=256) Kn[i>>7][i&127] *= inv[i>>7];
    __syncthreads();

    for (int n = wid; n < ND; n += 8) {
        const float4* Mr = (const float4*)(Mm + ((size_t)b*ND + n)*DD);
        float4 mv = Mr[lane];
        float vals[9];
        vals[8] = mv.x*mv.x + mv.y*mv.y + mv.z*mv.z + mv.w*mv.w;
        #pragma unroll
        for (int h=0;h<HH;h++){
            float4 kv = *(const float4*)&Kn[h][lane*4];
            vals[h] = mv.x*kv.x + mv.y*kv.y + mv.z*kv.z + mv.w*kv.w;
        }
        #pragma unroll
        for (int o=16;o;o>>=1)
            #pragma unroll
            for (int j=0;j<9;j++) vals[j] += __shfl_xor_sync(0xffffffffu, vals[j], o);
        if (lane==0){
            float im = 1.f / fmaxf(sqrtf(vals[8]), 1e-12f);
            #pragma unroll
            for (int h=0;h<HH;h++) cosm[h][n] = vals[h]*im;
        }
    }
    __syncthreads();

    float beta = softplusf_(braw[(size_t)b*HH + wid]);
    float mx = -1e30f;
    #pragma unroll
    for (int k=0;k<8;k++) mx = fmaxf(mx, beta*cosm[wid][lane+32*k]);
    #pragma unroll
    for (int o=16;o;o>>=1) mx = fmaxf(mx, __shfl_xor_sync(0xffffffffu, mx, o));
    float ev[8]; float sum=0.f;
    #pragma unroll
    for (int k=0;k<8;k++){ float e = expf(beta*cosm[wid][lane+32*k]-mx); ev[k]=e; sum+=e; }
    #pragma unroll
    for (int o=16;o;o>>=1) sum += __shfl_xor_sync(0xffffffffu, sum, o);
    float isum = 1.f/sum;
    #pragma unroll
    for (int k=0;k<8;k++) wout[((size_t)b*HH+wid)*ND + lane+32*k] = ev[k]*isum;
}

// ---------------- memory update ---------------------------------------------
__global__ void __launch_bounds__(128) mem_update(
    const float* __restrict__ Mp, const float* __restrict__ ww,
    const float* __restrict__ eraw, const float* __restrict__ araw, int ldk,
    float* __restrict__ Mo)
{
    int b = blockIdx.x, chunk = blockIdx.y;
    int tid = threadIdx.x;
    __shared__ float er[HH][DD], ad[HH][DD], ws[HH][32];
    for (int i=tid; i<HH*DD; i+=128){
        er[i>>7][i&127] = sigf(eraw[(size_t)b*ldk + i]);
        ad[i>>7][i&127] = tanhfast(araw[(size_t)b*ldk + i]);
    }
    for (int i=tid; i<HH*32; i+=128){
        int h=i>>5, nn=i&31;
        ws[h][nn] = ww[((size_t)b*HH+h)*ND + chunk*32+nn];
    }
    __syncthreads();
    for (int nn=0; nn<32; nn++){
        int n = chunk*32+nn;
        size_t off = ((size_t)b*ND+n)*DD + tid;
        float mp = Mp[off];
        float es=0.f, as=0.f;
        #pragma unroll
        for (int h=0;h<HH;h++){ float w=ws[h][nn]; es += w*er[h][tid]; as += w*ad[h][tid]; }
        Mo[off] = mp*(1.f-es) + as;
    }
}

// ---------------- read path: content + shift + sharpen ---------------------
__global__ void __launch_bounds__(256) content_r(
    const float* __restrict__ Mm,
    const float* __restrict__ Kraw, int ldk,
    const float* __restrict__ braw,
    const float* __restrict__ shraw,
    const float* __restrict__ garaw,
    float* __restrict__ wout)
{
    int b = blockIdx.x;
    __shared__ __align__(16) float Kn[HH][DD];
    __shared__ float cosm[HH][ND];
    __shared__ float inv[HH];
    __shared__ float s3[HH][3];
    int tid = threadIdx.x, wid = tid>>5, lane = tid&31;

    for (int i=tid; i<HH*DD; i+=256) Kn[i>>7][i&127] = Kraw[(size_t)b*ldk + i];
    __syncthreads();
    {
        float s=0.f;
        for (int d=lane; d<DD; d+=32){ float v=Kn[wid][d]; s+=v*v; }
        #pragma unroll
        for (int o=16;o;o>>=1) s += __shfl_xor_sync(0xffffffffu, s, o);
        if (lane==0) inv[wid] = 1.f / fmaxf(sqrtf(s), 1e-12f);
    }
    __syncthreads();
    for (int i=tid; i<HH*DD; i+=256) Kn[i>>7][i&127] *= inv[i>>7];
    __syncthreads();

    for (int n = wid; n < ND; n += 8) {
        const float4* Mr = (const float4*)(Mm + ((size_t)b*ND + n)*DD);
        float4 mv = Mr[lane];
        float vals[9];
        vals[8] = mv.x*mv.x + mv.y*mv.y + mv.z*mv.z + mv.w*mv.w;
        #pragma unroll
        for (int h=0;h<HH;h++){
            float4 kv = *(const float4*)&Kn[h][lane*4];
            vals[h] = mv.x*kv.x + mv.y*kv.y + mv.z*kv.z + mv.w*kv.w;
        }
        #pragma unroll
        for (int o=16;o;o>>=1)
            #pragma unroll
            for (int j=0;j<9;j++) vals[j] += __shfl_xor_sync(0xffffffffu, vals[j], o);
        if (lane==0){
            float im = 1.f / fmaxf(sqrtf(vals[8]), 1e-12f);
            #pragma unroll
            for (int h=0;h<HH;h++) cosm[h][n] = vals[h]*im;
        }
    }
    __syncthreads();

    float beta = softplusf_(braw[(size_t)b*HH + wid]);
    float mx = -1e30f;
    #pragma unroll
    for (int k=0;k<8;k++) mx = fmaxf(mx, beta*cosm[wid][lane+32*k]);
    #pragma unroll
    for (int o=16;o;o>>=1) mx = fmaxf(mx, __shfl_xor_sync(0xffffffffu, mx, o));
    float ev[8]; float sum=0.f;
    #pragma unroll
    for (int k=0;k<8;k++){ float e = expf(beta*cosm[wid][lane+32*k]-mx); ev[k]=e; sum+=e; }
    #pragma unroll
    for (int o=16;o;o>>=1) sum += __shfl_xor_sync(0xffffffffu, sum, o);
    float isum = 1.f/sum;
    __syncthreads();
    #pragma unroll
    for (int k=0;k<8;k++) cosm[wid][lane+32*k] = ev[k]*isum;

    if (lane==0){
        const float* sr = shraw + ((size_t)b*HH + wid)*3;
        float a=sr[0], bb2=sr[1], cc=sr[2];
        float m = fmaxf(a, fmaxf(bb2, cc));
        float ea=expf(a-m), eb=expf(bb2-m), ec=expf(cc-m);
        float is = 1.f/(ea+eb+ec);
        s3[wid][0]=ea*is; s3[wid][1]=eb*is; s3[wid][2]=ec*is;
    }
    __syncthreads();

    float sh0 = s3[wid][0], sh1 = s3[wid][1], sh2 = s3[wid][2];
    float gexp = 1.f + softplusf_(garaw[(size_t)b*HH + wid]);
    float wg[8]; float sum2=0.f;
    #pragma unroll
    for (int k=0;k<8;k++){
        int n = lane+32*k;
        float wsv = sh0*cosm[wid][(n+1)&255] + sh1*cosm[wid][n] + sh2*cosm[wid][(n-1)&255];
        float p = powf(wsv, gexp);
        wg[k]=p; sum2+=p;
    }
    #pragma unroll
    for (int o=16;o;o>>=1) sum2 += __shfl_xor_sync(0xffffffffu, sum2, o);
    float inv2 = 1.f/(sum2+1e-12f);
    #pragma unroll
    for (int k=0;k<8;k++) wout[((size_t)b*HH+wid)*ND + lane+32*k] = wg[k]*inv2;
}

// ---------------- r = w_r @ M ----------------------------------------------
__global__ void __launch_bounds__(128) read_r(
    const float* __restrict__ Mm, const float* __restrict__ wr, float* __restrict__ r)
{
    int b = blockIdx.x;
    int d = threadIdx.x;
    __shared__ float ws[HH][ND];
    for (int i=d; i<HH*ND; i+=128) ws[i>>8][i&255] = wr[(size_t)b*HH*ND + i];
    __syncthreads();
    float acc[HH];
    #pragma unroll
    for (int h=0;h<HH;h++) acc[h]=0.f;
    for (int n=0; n<ND; n++){
        float m = Mm[((size_t)b*ND+n)*DD + d];
        #pragma unroll
        for (int h=0;h<HH;h++) acc[h] += ws[h][n]*m;
    }
    #pragma unroll
    for (int h=0;h<HH;h++) r[((size_t)b*HH+h)*DD + d] = acc[h];
}

// ---------------- launcher ---------------------------------------------------
extern "C" void kernel_launch(void* const* d_in, const int* in_sizes, int n_in,
                              void* d_out, int out_size)
{
    const float* x      = (const float*)d_in[0];
    const float* h1     = (const float*)d_in[1];
    const float* c1     = (const float*)d_in[2];
    const float* h2     = (const float*)d_in[3];
    const float* c2     = (const float*)d_in[4];
    const float* r_prev = (const float*)d_in[6];
    const float* M_prev = (const float*)d_in[7];
    const float* W_ih1  = (const float*)d_in[8];
    const float* W_hh1  = (const float*)d_in[9];
    const float* b_ih1  = (const float*)d_in[10];
    const float* b_hh1  = (const float*)d_in[11];
    const float* W_ih2  = (const float*)d_in[12];
    const float* W_hh2  = (const float*)d_in[13];
    const float* b_ih2  = (const float*)d_in[14];
    const float* b_hh2  = (const float*)d_in[15];
    const float* W_rk   = (const float*)d_in[16];
    const float* b_rk   = (const float*)d_in[17];
    const float* W_wk   = (const float*)d_in[18];
    const float* b_wk   = (const float*)d_in[19];
    const float* W_rb   = (const float*)d_in[20];
    const float* b_rb   = (const float*)d_in[21];
    const float* W_wb   = (const float*)d_in[22];
    const float* b_wb   = (const float*)d_in[23];
    const float* W_er   = (const float*)d_in[24];
    const float* b_er   = (const float*)d_in[25];
    const float* W_ad   = (const float*)d_in[26];
    const float* b_ad   = (const float*)d_in[27];
    const float* W_sh   = (const float*)d_in[28];
    const float* b_sh   = (const float*)d_in[29];
    const float* W_ga   = (const float*)d_in[30];
    const float* b_ga   = (const float*)d_in[31];

    float* out = (float*)d_out;
    const size_t HC = (size_t)BSZ*CD;
    float* h1n = out;
    float* c1n = out + HC;
    float* h2n = out + 2*HC;
    float* c2n = out + 3*HC;
    float* wr  = out + 4*HC;
    float* rr  = wr + (size_t)BSZ*HH*ND;
    float* Mo  = rr + (size_t)BSZ*HH*DD;

    float* S = nullptr;
    cudaGetSymbolAddress((void**)&S, g_scratch);
    float* gates = S + GATES_OFF;
    float* heads = S + HEADS_OFF;
    float* WW    = S + WW_OFF;
    float* BR    = S + BR_OFF;
    float* BW    = S + BW_OFF;
    float* SHm   = S + SH_OFF;
    float* GA    = S + GA_OFF;

    dim3 ggrid(4096/64, BSZ/128);   // 64 x 4 = 256 CTAs

    // 1) LSTM1: gates = [x|r_prev|h1] @ [Wih1|Whh1]^T + b_ih1 + b_hh1
    {
        GemmCfg cfg{};
        cfg.s[0] = { x,      INPD, W_ih1,     W_ih1+(size_t)1024*1536,     W_ih1+(size_t)2048*1536,     W_ih1+(size_t)3072*1536,     1536, 512  };
        cfg.s[1] = { r_prev, 1024, W_ih1+512, W_ih1+(size_t)1024*1536+512, W_ih1+(size_t)2048*1536+512, W_ih1+(size_t)3072*1536+512, 1536, 1024 };
        cfg.s[2] = { h1,     1024, W_hh1,     W_hh1+(size_t)1024*1024,     W_hh1+(size_t)2048*1024,     W_hh1+(size_t)3072*1024,     1024, 1024 };
        cfg.nseg = 3; cfg.S = (512+1024+1024)/32;
        cfg.b0=b_ih1; cfg.b1=b_ih1+1024; cfg.b2=b_ih1+2048; cfg.b3=b_ih1+3072;
        cfg.e0=b_hh1; cfg.e1=b_hh1+1024; cfg.e2=b_hh1+2048; cfg.e3=b_hh1+3072;
        cfg.has2 = 1; cfg.C = gates; cfg.ldc = 4096;
        gemm_f16<<<ggrid, 256>>>(cfg);
    }
    lstm_pw<<<(BSZ*CD + 255)/256, 256>>>(gates, c1, h1n, c1n);

    // 2) LSTM2
    {
        GemmCfg cfg{};
        cfg.s[0] = { h1n, 1024, W_ih2, W_ih2+(size_t)1024*1024, W_ih2+(size_t)2048*1024, W_ih2+(size_t)3072*1024, 1024, 1024 };
        cfg.s[1] = { h2,  1024, W_hh2, W_hh2+(size_t)1024*1024, W_hh2+(size_t)2048*1024, W_hh2+(size_t)3072*1024, 1024, 1024 };
        cfg.nseg = 2; cfg.S = 2048/32;
        cfg.b0=b_ih2; cfg.b1=b_ih2+1024; cfg.b2=b_ih2+2048; cfg.b3=b_ih2+3072;
        cfg.e0=b_hh2; cfg.e1=b_hh2+1024; cfg.e2=b_hh2+2048; cfg.e3=b_hh2+3072;
        cfg.has2 = 1; cfg.C = gates; cfg.ldc = 4096;
        gemm_f16<<<ggrid, 256>>>(cfg);
    }
    lstm_pw<<<(BSZ*CD + 255)/256, 256>>>(gates, c2, h2n, c2n);

    // 3) fused head projections: heads = RK|WK|ER|AD
    {
        GemmCfg cfg{};
        cfg.s[0] = { h2n, 1024, W_rk, W_wk, W_er, W_ad, 1024, 1024 };
        cfg.nseg = 1; cfg.S = 1024/32;
        cfg.b0=b_rk; cfg.b1=b_wk; cfg.b2=b_er; cfg.b3=b_ad;
        cfg.e0=nullptr; cfg.e1=nullptr; cfg.e2=nullptr; cfg.e3=nullptr;
        cfg.has2 = 0; cfg.C = heads; cfg.ldc = 4096;
        gemm_f16<<<ggrid, 256>>>(cfg);
    }

    // 4) fused small heads (raw pre-activation)
    gemv_heads4<<<(BSZ*48*32 + 255)/256, 256>>>(h2n,
        W_rb, b_rb, W_wb, b_wb, W_sh, b_sh, W_ga, b_ga,
        BR, BW, SHm, GA);

    // 5) write-path content weights on M_prev (WK at heads+1024)
    content_w<<<BSZ, 256>>>(M_prev, heads + 1024, 4096, BW, WW);

    // 6) memory update -> Mo (ER at heads+2048, AD at heads+3072)
    mem_update<<<dim3(BSZ, 8), 128>>>(M_prev, WW, heads + 2048, heads + 3072, 4096, Mo);

    // 7) read-path (RK at heads+0)
    content_r<<<BSZ, 256>>>(Mo, heads, 4096, BR, SHm, GA, wr);

    // 8) r = w_r @ M
    read_r<<<BSZ, 128>>>(Mo, wr, rr);
}

// round 9
// speedup vs baseline: 1.0676x; 1.0676x over previous
#include <cuda_runtime.h>
#include <cuda_fp16.h>
#include <math.h>
#include <stdint.h>

#define BSZ 512
#define INPD 512
#define CD 1024
#define ND 256
#define DD 128
#define HH 8

// ---------------- scratch (single device global, no allocations) ----------
#define GATES_OFF 0
#define HEADS_OFF 2097152
#define WW_OFF    4194304
#define BR_OFF    5242880
#define BW_OFF    5246976
#define SH_OFF    5251072
#define GA_OFF    5263360
#define FP16_OFF  5267456            // below here: fp16 area (as half*)
#define SCRATCH_TOTAL 18243584       // floats (~73MB)

// fp16 area offsets (in halves)
#define WIH1_H 0u
#define WHH1_H 6291456u
#define WIH2_H 10485760u
#define WHH2_H 14680064u
#define WHD_H  18874368u
#define XH     23068672u
#define RH     23330816u
#define H1H    23855104u
#define H2H    24379392u
#define H1NH   24903680u
#define H2NH   25427968u

__device__ __align__(16) float g_scratch[SCRATCH_TOTAL];

__device__ __forceinline__ float sigf(float x){ return __fdividef(1.f, 1.f + __expf(-x)); }
__device__ __forceinline__ float tanhfast(float x){
    float e = __expf(2.f*x);
    return 1.f - __fdividef(2.f, e + 1.f);
}
__device__ __forceinline__ float softplusf_(float x){ return x>20.f ? x : log1pf(expf(x)); }

// ---------------- batched f32 -> f16 conversion -----------------------------
struct CvtSeg { const float* src; __half* dst; };
struct CvtCfg { CvtSeg s[12]; int off[13]; int total8; };

__global__ void cvt_f2h(CvtCfg cfg)
{
    int i = blockIdx.x*blockDim.x + threadIdx.x;
    if (i >= cfg.total8) return;
    int lo = 0;
    #pragma unroll
    for (int k=1;k<=12;k++) if (i >= cfg.off[k]) lo = k;
    int j = i - cfg.off[lo];
    const float4* sp = (const float4*)(cfg.s[lo].src) + 2*(size_t)j;
    float4 u = sp[0], v = sp[1];
    __half2 h0 = __floats2half2_rn(u.x,u.y), h1 = __floats2half2_rn(u.z,u.w);
    __half2 h2 = __floats2half2_rn(v.x,v.y), h3 = __floats2half2_rn(v.z,v.w);
    uint4 o;
    o.x = *(uint32_t*)&h0; o.y = *(uint32_t*)&h1;
    o.z = *(uint32_t*)&h2; o.w = *(uint32_t*)&h3;
    *((uint4*)(cfg.s[lo].dst) + j) = o;
}

// =====================  fp16 tensor-core GEMM (cp.async, 3-stage) ===========
// C[M,N] = sum_seg A_seg[M,Kseg] @ W_seg[N,Kseg]^T + bias (+bias2)
// BM=128, BN=64, BK=32(halves). 256 threads, 8 warps (4m x 2n), warp 32x32.
// fp16 global operands, cp.async.cg 16B direct to swizzled smem, ldmatrix, mma.

struct GemmSeg {
    const __half* A; int lda;
    const __half* W0; const __half* W1; const __half* W2; const __half* W3;
    int ldw; int klen;
};
struct GemmCfg {
    GemmSeg s[3];
    int nseg; int S;
    const float* b0; const float* b1; const float* b2; const float* b3;
    const float* e0; const float* e1; const float* e2; const float* e3;
    int has2;
    float* C; int ldc;
};

// word (uint32 = 2 halves) position: row r, word w (0..15); XOR on bits 2-3.
__device__ __forceinline__ int swzw(int r, int w){
    return (r<<4) + (w ^ (((r>>1)&3)<<2));
}

__device__ __forceinline__ void stage_of(const GemmCfg& cfg, int s, int& seg, int& k0){
    int acc = 0;
    #pragma unroll
    for (int i=0;i<3;i++){
        if (i >= cfg.nseg) break;
        int ns = cfg.s[i].klen >> 5;
        if (s < acc + ns){ seg = i; k0 = (s - acc) << 5; return; }
        acc += ns;
    }
    seg = 0; k0 = 0;
}

__device__ __forceinline__ void issue_stage(const GemmSeg& sg, int bm, int bn,
                                            int t, int k0, uint32_t aBase, uint32_t bBase)
{
    int q = bn>>10;
    const __half* Wq = (q==0)?sg.W0:(q==1)?sg.W1:(q==2)?sg.W2:sg.W3;
    int row = t>>2, ch = t&3;
    const __half* a0 = sg.A + (size_t)(bm+row)*sg.lda + k0 + ch*8;
    const __half* a1 = a0 + (size_t)64*sg.lda;
    const __half* b0 = Wq + (size_t)((bn&1023)+row)*sg.ldw + k0 + ch*8;
    uint32_t d0 = aBase + 4*swzw(row,    ch*4);
    uint32_t d1 = aBase + 4*swzw(row+64, ch*4);
    uint32_t db = bBase + 4*swzw(row,    ch*4);
    asm volatile("cp.async.cg.shared.global [%0], [%1], 16;\n" :: "r"(d0), "l"(a0) : "memory");
    asm volatile("cp.async.cg.shared.global [%0], [%1], 16;\n" :: "r"(d1), "l"(a1) : "memory");
    asm volatile("cp.async.cg.shared.global [%0], [%1], 16;\n" :: "r"(db), "l"(b0) : "memory");
}

__device__ __forceinline__ void ldm_x4(uint32_t& r0, uint32_t& r1, uint32_t& r2, uint32_t& r3,
                                       uint32_t addr){
    asm volatile("ldmatrix.sync.aligned.m8n8.x4.shared.b16 {%0,%1,%2,%3}, [%4];"
        : "=r"(r0), "=r"(r1), "=r"(r2), "=r"(r3) : "r"(addr));
}

__global__ void __launch_bounds__(256,2) gemm_f16(GemmCfg cfg)
{
    __shared__ __align__(16) uint32_t As[3][2048];  // 3 x (128 rows x 16 words)
    __shared__ __align__(16) uint32_t Bs[3][1024];  // 3 x ( 64 rows x 16 words)
    const int tid = threadIdx.x;
    const int wid = tid>>5, lane = tid&31;
    const int bm = blockIdx.y*128, bn = blockIdx.x*64;
    const int wm = (wid>>1)*32, wn = (wid&1)*32;
    const int g = lane>>2, tig = lane&3;
    const int grp = lane>>3, rowin = lane&7;

    const uint32_t smA = (uint32_t)__cvta_generic_to_shared(&As[0][0]);
    const uint32_t smB = (uint32_t)__cvta_generic_to_shared(&Bs[0][0]);

    float acc[2][4][4];
    #pragma unroll
    for (int i=0;i<2;i++)
        #pragma unroll
        for (int j=0;j<4;j++)
            #pragma unroll
            for (int t=0;t<4;t++) acc[i][j][t]=0.f;

    int seg, k0;
    // prologue: issue stages 0 and 1
    stage_of(cfg, 0, seg, k0);
    issue_stage(cfg.s[seg], bm, bn, tid, k0, smA, smB);
    asm volatile("cp.async.commit_group;\n" ::: "memory");
    stage_of(cfg, 1, seg, k0);
    issue_stage(cfg.s[seg], bm, bn, tid, k0, smA + 8192, smB + 4096);
    asm volatile("cp.async.commit_group;\n" ::: "memory");

    for (int s = 0; s < cfg.S; s++){
        if (s+1 < cfg.S) asm volatile("cp.async.wait_group 1;\n" ::: "memory");
        else             asm volatile("cp.async.wait_group 0;\n" ::: "memory");
        __syncthreads();

        if (s+2 < cfg.S){
            stage_of(cfg, s+2, seg, k0);
            int b2 = (s+2)%3;
            issue_stage(cfg.s[seg], bm, bn, tid, k0, smA + b2*8192, smB + b2*4096);
            asm volatile("cp.async.commit_group;\n" ::: "memory");
        }

        const int buf = s%3;
        const uint32_t aBase = smA + buf*8192;
        const uint32_t bBase = smB + buf*4096;

        #pragma unroll
        for (int kk=0;kk<2;kk++){
            const int kb = kk*8;
            uint32_t af[2][4], bf[2][4];
            #pragma unroll
            for (int mf=0;mf<2;mf++){
                int arow  = wm + mf*16 + ((grp&1)<<3) + rowin;
                int aword = kb + ((grp>>1)<<2);
                uint32_t aw = (arow<<4) + (aword ^ (((arow>>1)&3)<<2));
                ldm_x4(af[mf][0], af[mf][1], af[mf][2], af[mf][3], aBase + 4*aw);
            }
            #pragma unroll
            for (int nf2=0;nf2<2;nf2++){
                int brow  = wn + nf2*16 + ((grp>>1)<<3) + rowin;
                int bword = kb + ((grp&1)<<2);
                uint32_t bw = (brow<<4) + (bword ^ (((brow>>1)&3)<<2));
                ldm_x4(bf[nf2][0], bf[nf2][1], bf[nf2][2], bf[nf2][3], bBase + 4*bw);
            }
            #pragma unroll
            for (int mf=0;mf<2;mf++)
                #pragma unroll
                for (int nf=0;nf<4;nf++)
                    asm volatile(
                        "mma.sync.aligned.m16n8k16.row.col.f32.f16.f16.f32 "
                        "{%0,%1,%2,%3},{%4,%5,%6,%7},{%8,%9},{%0,%1,%2,%3};"
                        : "+f"(acc[mf][nf][0]), "+f"(acc[mf][nf][1]),
                          "+f"(acc[mf][nf][2]), "+f"(acc[mf][nf][3])
                        : "r"(af[mf][0]), "r"(af[mf][1]), "r"(af[mf][2]), "r"(af[mf][3]),
                          "r"(bf[nf>>1][(nf&1)*2]), "r"(bf[nf>>1][(nf&1)*2+1]));
        }
    }

    // epilogue
    const int q = bn>>10;
    const float* bq = (q==0)?cfg.b0:(q==1)?cfg.b1:(q==2)?cfg.b2:cfg.b3;
    const float* eq = (q==0)?cfg.e0:(q==1)?cfg.e1:(q==2)?cfg.e2:cfg.e3;
    #pragma unroll
    for (int mf=0;mf<2;mf++){
        int row = bm + wm + mf*16 + g;
        #pragma unroll
        for (int nf=0;nf<4;nf++){
            int col = bn + wn + nf*8 + 2*tig;
            int cq = col & 1023;
            float b0v = bq[cq], b1v = bq[cq+1];
            if (cfg.has2){ b0v += eq[cq]; b1v += eq[cq+1]; }
            float2 v0; v0.x = acc[mf][nf][0] + b0v; v0.y = acc[mf][nf][1] + b1v;
            float2 v1; v1.x = acc[mf][nf][2] + b0v; v1.y = acc[mf][nf][3] + b1v;
            *(float2*)&cfg.C[(size_t)row*cfg.ldc + col]     = v0;
            *(float2*)&cfg.C[(size_t)(row+8)*cfg.ldc + col] = v1;
        }
    }
}

// ---------------- LSTM pointwise (gate order i,f,g,o) ----------------------
__global__ void lstm_pw(const float* __restrict__ g, const float* __restrict__ cprev,
                        float* __restrict__ hout, float* __restrict__ cout,
                        __half* __restrict__ hout16)
{
    int idx = blockIdx.x*blockDim.x + threadIdx.x;
    if (idx >= BSZ*CD) return;
    int bb = idx >> 10, cc = idx & 1023;
    const float* gr = g + (size_t)bb*4096;
    float gi = sigf(gr[cc]);
    float gf = sigf(gr[1024+cc]);
    float gg = tanhfast(gr[2048+cc]);
    float go = sigf(gr[3072+cc]);
    float cn = gf*cprev[idx] + gi*gg;
    cout[idx] = cn;
    float h = go * tanhfast(cn);
    hout[idx] = h;
    hout16[idx] = __float2half(h);
}

// ---------------- fused small heads -----------------------------------------
__global__ void gemv_heads4(const float* __restrict__ h,
                            const float* __restrict__ Wrb, const float* __restrict__ brb,
                            const float* __restrict__ Wwb, const float* __restrict__ bwb,
                            const float* __restrict__ Wsh, const float* __restrict__ bsh,
                            const float* __restrict__ Wga, const float* __restrict__ bga,
                            float* __restrict__ orb, float* __restrict__ owb,
                            float* __restrict__ osh, float* __restrict__ oga)
{
    int gw = (blockIdx.x*blockDim.x + threadIdx.x) >> 5;
    int lane = threadIdx.x & 31;
    if (gw >= BSZ*48) return;
    int bidx = gw / 48, t = gw - bidx*48;
    const float* W; const float* bias; float* out; int n; int nout;
    if (t < 8)       { W=Wrb; bias=brb; out=orb; n=t;     nout=8;  }
    else if (t < 16) { W=Wwb; bias=bwb; out=owb; n=t-8;   nout=8;  }
    else if (t < 40) { W=Wsh; bias=bsh; out=osh; n=t-16;  nout=24; }
    else             { W=Wga; bias=bga; out=oga; n=t-40;  nout=8;  }
    const float4* hv = (const float4*)(h + (size_t)bidx*CD);
    const float4* wv = (const float4*)(W + (size_t)n*CD);
    float s = 0.f;
    #pragma unroll 4
    for (int i=lane; i<CD/4; i+=32){
        float4 a=hv[i], w=wv[i];
        s += a.x*w.x + a.y*w.y + a.z*w.z + a.w*w.w;
    }
    #pragma unroll
    for (int o=16;o;o>>=1) s += __shfl_xor_sync(0xffffffffu, s, o);
    if (lane==0) out[(size_t)bidx*nout + n] = s + bias[n];
}

// ---------------- content addressing (write path) --------------------------
__global__ void __launch_bounds__(256) content_w(
    const float* __restrict__ Mm,
    const float* __restrict__ Kraw, int ldk,
    const float* __restrict__ braw,
    float* __restrict__ wout)
{
    int b = blockIdx.x;
    __shared__ __align__(16) float Kn[HH][DD];
    __shared__ float cosm[HH][ND];
    __shared__ float inv[HH];
    int tid = threadIdx.x, wid = tid>>5, lane = tid&31;

    for (int i=tid; i<HH*DD; i+=256) Kn[i>>7][i&127] = Kraw[(size_t)b*ldk + i];
    __syncthreads();
    {
        float s=0.f;
        for (int d=lane; d<DD; d+=32){ float v=Kn[wid][d]; s+=v*v; }
        #pragma unroll
        for (int o=16;o;o>>=1) s += __shfl_xor_sync(0xffffffffu, s, o);
        if (lane==0) inv[wid] = 1.f / fmaxf(sqrtf(s), 1e-12f);
    }
    __syncthreads();
    for (int i=tid; i<HH*DD; i+=256) Kn[i>>7][i&127] *= inv[i>>7];
    __syncthreads();

    for (int n = wid; n < ND; n += 8) {
        const float4* Mr = (const float4*)(Mm + ((size_t)b*ND + n)*DD);
        float4 mv = Mr[lane];
        float vals[9];
        vals[8] = mv.x*mv.x + mv.y*mv.y + mv.z*mv.z + mv.w*mv.w;
        #pragma unroll
        for (int h=0;h<HH;h++){
            float4 kv = *(const float4*)&Kn[h][lane*4];
            vals[h] = mv.x*kv.x + mv.y*kv.y + mv.z*kv.z + mv.w*kv.w;
        }
        #pragma unroll
        for (int o=16;o;o>>=1)
            #pragma unroll
            for (int j=0;j<9;j++) vals[j] += __shfl_xor_sync(0xffffffffu, vals[j], o);
        if (lane==0){
            float im = 1.f / fmaxf(sqrtf(vals[8]), 1e-12f);
            #pragma unroll
            for (int h=0;h<HH;h++) cosm[h][n] = vals[h]*im;
        }
    }
    __syncthreads();

    float beta = softplusf_(braw[(size_t)b*HH + wid]);
    float mx = -1e30f;
    #pragma unroll
    for (int k=0;k<8;k++) mx = fmaxf(mx, beta*cosm[wid][lane+32*k]);
    #pragma unroll
    for (int o=16;o;o>>=1) mx = fmaxf(mx, __shfl_xor_sync(0xffffffffu, mx, o));
    float ev[8]; float sum=0.f;
    #pragma unroll
    for (int k=0;k<8;k++){ float e = expf(beta*cosm[wid][lane+32*k]-mx); ev[k]=e; sum+=e; }
    #pragma unroll
    for (int o=16;o;o>>=1) sum += __shfl_xor_sync(0xffffffffu, sum, o);
    float isum = 1.f/sum;
    #pragma unroll
    for (int k=0;k<8;k++) wout[((size_t)b*HH+wid)*ND + lane+32*k] = ev[k]*isum;
}

// ---------------- memory update ---------------------------------------------
__global__ void __launch_bounds__(128) mem_update(
    const float* __restrict__ Mp, const float* __restrict__ ww,
    const float* __restrict__ eraw, const float* __restrict__ araw, int ldk,
    float* __restrict__ Mo)
{
    int b = blockIdx.x, chunk = blockIdx.y;
    int tid = threadIdx.x;
    __shared__ float er[HH][DD], ad[HH][DD], ws[HH][32];
    for (int i=tid; i<HH*DD; i+=128){
        er[i>>7][i&127] = sigf(eraw[(size_t)b*ldk + i]);
        ad[i>>7][i&127] = tanhfast(araw[(size_t)b*ldk + i]);
    }
    for (int i=tid; i<HH*32; i+=128){
        int h=i>>5, nn=i&31;
        ws[h][nn] = ww[((size_t)b*HH+h)*ND + chunk*32+nn];
    }
    __syncthreads();
    for (int nn=0; nn<32; nn++){
        int n = chunk*32+nn;
        size_t off = ((size_t)b*ND+n)*DD + tid;
        float mp = Mp[off];
        float es=0.f, as=0.f;
        #pragma unroll
        for (int h=0;h<HH;h++){ float w=ws[h][nn]; es += w*er[h][tid]; as += w*ad[h][tid]; }
        Mo[off] = mp*(1.f-es) + as;
    }
}

// ---------------- read path: content + shift + sharpen ---------------------
__global__ void __launch_bounds__(256) content_r(
    const float* __restrict__ Mm,
    const float* __restrict__ Kraw, int ldk,
    const float* __restrict__ braw,
    const float* __restrict__ shraw,
    const float* __restrict__ garaw,
    float* __restrict__ wout)
{
    int b = blockIdx.x;
    __shared__ __align__(16) float Kn[HH][DD];
    __shared__ float cosm[HH][ND];
    __shared__ float inv[HH];
    __shared__ float s3[HH][3];
    int tid = threadIdx.x, wid = tid>>5, lane = tid&31;

    for (int i=tid; i<HH*DD; i+=256) Kn[i>>7][i&127] = Kraw[(size_t)b*ldk + i];
    __syncthreads();
    {
        float s=0.f;
        for (int d=lane; d<DD; d+=32){ float v=Kn[wid][d]; s+=v*v; }
        #pragma unroll
        for (int o=16;o;o>>=1) s += __shfl_xor_sync(0xffffffffu, s, o);
        if (lane==0) inv[wid] = 1.f / fmaxf(sqrtf(s), 1e-12f);
    }
    __syncthreads();
    for (int i=tid; i<HH*DD; i+=256) Kn[i>>7][i&127] *= inv[i>>7];
    __syncthreads();

    for (int n = wid; n < ND; n += 8) {
        const float4* Mr = (const float4*)(Mm + ((size_t)b*ND + n)*DD);
        float4 mv = Mr[lane];
        float vals[9];
        vals[8] = mv.x*mv.x + mv.y*mv.y + mv.z*mv.z + mv.w*mv.w;
        #pragma unroll
        for (int h=0;h<HH;h++){
            float4 kv = *(const float4*)&Kn[h][lane*4];
            vals[h] = mv.x*kv.x + mv.y*kv.y + mv.z*kv.z + mv.w*kv.w;
        }
        #pragma unroll
        for (int o=16;o;o>>=1)
            #pragma unroll
            for (int j=0;j<9;j++) vals[j] += __shfl_xor_sync(0xffffffffu, vals[j], o);
        if (lane==0){
            float im = 1.f / fmaxf(sqrtf(vals[8]), 1e-12f);
            #pragma unroll
            for (int h=0;h<HH;h++) cosm[h][n] = vals[h]*im;
        }
    }
    __syncthreads();

    float beta = softplusf_(braw[(size_t)b*HH + wid]);
    float mx = -1e30f;
    #pragma unroll
    for (int k=0;k<8;k++) mx = fmaxf(mx, beta*cosm[wid][lane+32*k]);
    #pragma unroll
    for (int o=16;o;o>>=1) mx = fmaxf(mx, __shfl_xor_sync(0xffffffffu, mx, o));
    float ev[8]; float sum=0.f;
    #pragma unroll
    for (int k=0;k<8;k++){ float e = expf(beta*cosm[wid][lane+32*k]-mx); ev[k]=e; sum+=e; }
    #pragma unroll
    for (int o=16;o;o>>=1) sum += __shfl_xor_sync(0xffffffffu, sum, o);
    float isum = 1.f/sum;
    __syncthreads();
    #pragma unroll
    for (int k=0;k<8;k++) cosm[wid][lane+32*k] = ev[k]*isum;

    if (lane==0){
        const float* sr = shraw + ((size_t)b*HH + wid)*3;
        float a=sr[0], bb2=sr[1], cc=sr[2];
        float m = fmaxf(a, fmaxf(bb2, cc));
        float ea=expf(a-m), eb=expf(bb2-m), ec=expf(cc-m);
        float is = 1.f/(ea+eb+ec);
        s3[wid][0]=ea*is; s3[wid][1]=eb*is; s3[wid][2]=ec*is;
    }
    __syncthreads();

    float sh0 = s3[wid][0], sh1 = s3[wid][1], sh2 = s3[wid][2];
    float gexp = 1.f + softplusf_(garaw[(size_t)b*HH + wid]);
    float wg[8]; float sum2=0.f;
    #pragma unroll
    for (int k=0;k<8;k++){
        int n = lane+32*k;
        float wsv = sh0*cosm[wid][(n+1)&255] + sh1*cosm[wid][n] + sh2*cosm[wid][(n-1)&255];
        float p = powf(wsv, gexp);
        wg[k]=p; sum2+=p;
    }
    #pragma unroll
    for (int o=16;o;o>>=1) sum2 += __shfl_xor_sync(0xffffffffu, sum2, o);
    float inv2 = 1.f/(sum2+1e-12f);
    #pragma unroll
    for (int k=0;k<8;k++) wout[((size_t)b*HH+wid)*ND + lane+32*k] = wg[k]*inv2;
}

// ---------------- r = w_r @ M ----------------------------------------------
__global__ void __launch_bounds__(128) read_r(
    const float* __restrict__ Mm, const float* __restrict__ wr, float* __restrict__ r)
{
    int b = blockIdx.x;
    int d = threadIdx.x;
    __shared__ float ws[HH][ND];
    for (int i=d; i<HH*ND; i+=128) ws[i>>8][i&255] = wr[(size_t)b*HH*ND + i];
    __syncthreads();
    float acc[HH];
    #pragma unroll
    for (int h=0;h<HH;h++) acc[h]=0.f;
    for (int n=0; n<ND; n++){
        float m = Mm[((size_t)b*ND+n)*DD + d];
        #pragma unroll
        for (int h=0;h<HH;h++) acc[h] += ws[h][n]*m;
    }
    #pragma unroll
    for (int h=0;h<HH;h++) r[((size_t)b*HH+h)*DD + d] = acc[h];
}

// ---------------- launcher ---------------------------------------------------
extern "C" void kernel_launch(void* const* d_in, const int* in_sizes, int n_in,
                              void* d_out, int out_size)
{
    const float* x      = (const float*)d_in[0];
    const float* h1     = (const float*)d_in[1];
    const float* c1     = (const float*)d_in[2];
    const float* h2     = (const float*)d_in[3];
    const float* c2     = (const float*)d_in[4];
    const float* r_prev = (const float*)d_in[6];
    const float* M_prev = (const float*)d_in[7];
    const float* W_ih1  = (const float*)d_in[8];
    const float* W_hh1  = (const float*)d_in[9];
    const float* b_ih1  = (const float*)d_in[10];
    const float* b_hh1  = (const float*)d_in[11];
    const float* W_ih2  = (const float*)d_in[12];
    const float* W_hh2  = (const float*)d_in[13];
    const float* b_ih2  = (const float*)d_in[14];
    const float* b_hh2  = (const float*)d_in[15];
    const float* W_rk   = (const float*)d_in[16];
    const float* b_rk   = (const float*)d_in[17];
    const float* W_wk   = (const float*)d_in[18];
    const float* b_wk   = (const float*)d_in[19];
    const float* W_rb   = (const float*)d_in[20];
    const float* b_rb   = (const float*)d_in[21];
    const float* W_wb   = (const float*)d_in[22];
    const float* b_wb   = (const float*)d_in[23];
    const float* W_er   = (const float*)d_in[24];
    const float* b_er   = (const float*)d_in[25];
    const float* W_ad   = (const float*)d_in[26];
    const float* b_ad   = (const float*)d_in[27];
    const float* W_sh   = (const float*)d_in[28];
    const float* b_sh   = (const float*)d_in[29];
    const float* W_ga   = (const float*)d_in[30];
    const float* b_ga   = (const float*)d_in[31];

    float* out = (float*)d_out;
    const size_t HC = (size_t)BSZ*CD;
    float* h1n = out;
    float* c1n = out + HC;
    float* h2n = out + 2*HC;
    float* c2n = out + 3*HC;
    float* wr  = out + 4*HC;
    float* rr  = wr + (size_t)BSZ*HH*ND;
    float* Mo  = rr + (size_t)BSZ*HH*DD;

    float* S = nullptr;
    cudaGetSymbolAddress((void**)&S, g_scratch);
    float* gates = S + GATES_OFF;
    float* heads = S + HEADS_OFF;
    float* WW    = S + WW_OFF;
    float* BR    = S + BR_OFF;
    float* BW    = S + BW_OFF;
    float* SHm   = S + SH_OFF;
    float* GA    = S + GA_OFF;
    __half* Hh   = (__half*)(S + FP16_OFF);

    // 0) batched f32->f16 conversion (weights + input activations)
    {
        CvtCfg c{};
        const int n8[12] = {786432, 524288, 524288, 524288,
                            131072, 131072, 131072, 131072,
                            32768, 65536, 65536, 65536};
        const float* srcs[12] = {W_ih1, W_hh1, W_ih2, W_hh2,
                                 W_rk, W_wk, W_er, W_ad,
                                 x, r_prev, h1, h2};
        const unsigned dsts[12] = {WIH1_H, WHH1_H, WIH2_H, WHH2_H,
                                   WHD_H, WHD_H+1048576u, WHD_H+2097152u, WHD_H+3145728u,
                                   XH, RH, H1H, H2H};
        int acc = 0;
        for (int i=0;i<12;i++){
            c.s[i].src = srcs[i];
            c.s[i].dst = Hh + dsts[i];
            c.off[i] = acc;
            acc += n8[i];
        }
        c.off[12] = acc;
        c.total8 = acc;   // 3,112,960
        cvt_f2h<<<(c.total8 + 255)/256, 256>>>(c);
    }

    dim3 ggrid(4096/64, BSZ/128);   // 256 CTAs

    // 1) LSTM1: gates = [x|r_prev|h1] @ [Wih1|Whh1]^T + b_ih1 + b_hh1
    {
        GemmCfg cfg{};
        const __half* wih1 = Hh + WIH1_H;
        const __half* whh1 = Hh + WHH1_H;
        cfg.s[0] = { Hh+XH,  512,  wih1,     wih1+(size_t)1024*1536,     wih1+(size_t)2048*1536,     wih1+(size_t)3072*1536,     1536, 512  };
        cfg.s[1] = { Hh+RH,  1024, wih1+512, wih1+(size_t)1024*1536+512, wih1+(size_t)2048*1536+512, wih1+(size_t)3072*1536+512, 1536, 1024 };
        cfg.s[2] = { Hh+H1H, 1024, whh1,     whh1+(size_t)1024*1024,     whh1+(size_t)2048*1024,     whh1+(size_t)3072*1024,     1024, 1024 };
        cfg.nseg = 3; cfg.S = (512+1024+1024)/32;
        cfg.b0=b_ih1; cfg.b1=b_ih1+1024; cfg.b2=b_ih1+2048; cfg.b3=b_ih1+3072;
        cfg.e0=b_hh1; cfg.e1=b_hh1+1024; cfg.e2=b_hh1+2048; cfg.e3=b_hh1+3072;
        cfg.has2 = 1; cfg.C = gates; cfg.ldc = 4096;
        gemm_f16<<<ggrid, 256>>>(cfg);
    }
    lstm_pw<<<(BSZ*CD + 255)/256, 256>>>(gates, c1, h1n, c1n, Hh+H1NH);

    // 2) LSTM2
    {
        GemmCfg cfg{};
        const __half* wih2 = Hh + WIH2_H;
        const __half* whh2 = Hh + WHH2_H;
        cfg.s[0] = { Hh+H1NH, 1024, wih2, wih2+(size_t)1024*1024, wih2+(size_t)2048*1024, wih2+(size_t)3072*1024, 1024, 1024 };
        cfg.s[1] = { Hh+H2H,  1024, whh2, whh2+(size_t)1024*1024, whh2+(size_t)2048*1024, whh2+(size_t)3072*1024, 1024, 1024 };
        cfg.nseg = 2; cfg.S = 2048/32;
        cfg.b0=b_ih2; cfg.b1=b_ih2+1024; cfg.b2=b_ih2+2048; cfg.b3=b_ih2+3072;
        cfg.e0=b_hh2; cfg.e1=b_hh2+1024; cfg.e2=b_hh2+2048; cfg.e3=b_hh2+3072;
        cfg.has2 = 1; cfg.C = gates; cfg.ldc = 4096;
        gemm_f16<<<ggrid, 256>>>(cfg);
    }
    lstm_pw<<<(BSZ*CD + 255)/256, 256>>>(gates, c2, h2n, c2n, Hh+H2NH);

    // 3) fused head projections: heads = RK|WK|ER|AD
    {
        GemmCfg cfg{};
        const __half* whd = Hh + WHD_H;
        cfg.s[0] = { Hh+H2NH, 1024, whd, whd+1048576u, whd+2097152u, whd+3145728u, 1024, 1024 };
        cfg.nseg = 1; cfg.S = 1024/32;
        cfg.b0=b_rk; cfg.b1=b_wk; cfg.b2=b_er; cfg.b3=b_ad;
        cfg.e0=nullptr; cfg.e1=nullptr; cfg.e2=nullptr; cfg.e3=nullptr;
        cfg.has2 = 0; cfg.C = heads; cfg.ldc = 4096;
        gemm_f16<<<ggrid, 256>>>(cfg);
    }

    // 4) fused small heads (raw pre-activation)
    gemv_heads4<<<(BSZ*48*32 + 255)/256, 256>>>(h2n,
        W_rb, b_rb, W_wb, b_wb, W_sh, b_sh, W_ga, b_ga,
        BR, BW, SHm, GA);

    // 5) write-path content weights on M_prev (WK at heads+1024)
    content_w<<<BSZ, 256>>>(M_prev, heads + 1024, 4096, BW, WW);

    // 6) memory update -> Mo (ER at heads+2048, AD at heads+3072)
    mem_update<<<dim3(BSZ, 8), 128>>>(M_prev, WW, heads + 2048, heads + 3072, 4096, Mo);

    // 7) read-path (RK at heads+0)
    content_r<<<BSZ, 256>>>(Mo, heads, 4096, BR, SHm, GA, wr);

    // 8) r = w_r @ M
    read_r<<<BSZ, 128>>>(Mo, wr, rr);
}

// round 10
// speedup vs baseline: 1.1968x; 1.1211x over previous
#include <cuda_runtime.h>
#include <cuda_fp16.h>
#include <math.h>
#include <stdint.h>

#define BSZ 512
#define INPD 512
#define CD 1024
#define ND 256
#define DD 128
#define HH 8

// ---------------- scratch (single device global, no allocations) ----------
#define GATES_OFF 0
#define HEADS_OFF 2097152
#define WW_OFF    4194304
#define BR_OFF    5242880
#define BW_OFF    5246976
#define SH_OFF    5251072
#define GA_OFF    5263360
#define FP16_OFF  5267456            // below here: fp16 area (as half*)
#define SCRATCH_TOTAL 18243584       // floats (~73MB)

// fp16 area offsets (in halves)
#define WCAT1_H 0u            // [4096][2560]  = [Wih1|Whh1]
#define WCAT2_H 10485760u     // [4096][2048]  = [Wih2|Whh2]
#define WHD_H   18874368u     // [4096][1024]  = Wrk|Wwk|Wer|Wad stacked
#define ACAT1_H 23068672u     // [512][2560]   = [x|r_prev|h1]
#define ACAT2_H 24379392u     // [512][2048]   = [h1n|h2]
#define H2NH    25427968u     // [512][1024]   = h2n

__device__ __align__(16) float g_scratch[SCRATCH_TOTAL];

__device__ __forceinline__ float sigf(float x){ return __fdividef(1.f, 1.f + __expf(-x)); }
__device__ __forceinline__ float tanhfast(float x){
    float e = __expf(2.f*x);
    return 1.f - __fdividef(2.f, e + 1.f);
}
__device__ __forceinline__ float softplusf_(float x){ return x>20.f ? x : log1pf(expf(x)); }

// ---------------- batched f32 -> f16 conversion with row remap --------------
// chunk = 8 elems. dst chunk = (j/cpr)*drc + doff + j%cpr
struct CvtSeg { const float* src; __half* dst; int cpr, drc, doff; };
struct CvtCfg { CvtSeg s[13]; int off[14]; int total8; };

__global__ void cvt_f2h(CvtCfg cfg)
{
    int i = blockIdx.x*blockDim.x + threadIdx.x;
    if (i >= cfg.total8) return;
    int lo = 0;
    #pragma unroll
    for (int k=1;k<=13;k++) if (i >= cfg.off[k]) lo = k;
    int j = i - cfg.off[lo];
    const float* src = cfg.s[lo].src;
    __half* dst = cfg.s[lo].dst;
    int cpr = cfg.s[lo].cpr, drc = cfg.s[lo].drc, doff = cfg.s[lo].doff;
    int row = j / cpr;
    int col = j - row*cpr;
    size_t dchunk = (size_t)row*drc + doff + col;
    const float4* sp = (const float4*)src + 2*(size_t)j;
    float4 u = sp[0], v = sp[1];
    __half2 h0 = __floats2half2_rn(u.x,u.y), h1 = __floats2half2_rn(u.z,u.w);
    __half2 h2 = __floats2half2_rn(v.x,v.y), h3 = __floats2half2_rn(v.z,v.w);
    uint4 o;
    o.x = *(uint32_t*)&h0; o.y = *(uint32_t*)&h1;
    o.z = *(uint32_t*)&h2; o.w = *(uint32_t*)&h3;
    *((uint4*)(dst + 8*dchunk)) = o;
}

// =====================  fp16 tensor-core GEMM (cp.async, 3-stage) ===========
// C[M,N] = A[M,K] @ W[N,K]^T + bias (+bias2).  Contiguous K, single W.
// BM=128, BN=64, BK=32(halves). 256 threads, 8 warps (4m x 2n), warp 32x32.

// word (uint32 = 2 halves) position: row r, word w (0..15); XOR on bits 2-3.
__device__ __forceinline__ int swzw(int r, int w){
    return (r<<4) + (w ^ (((r>>1)&3)<<2));
}

__device__ __forceinline__ void issue_stage(const __half* A, int lda,
                                            const __half* W, int ldw,
                                            int bm, int bn, int t, int k0,
                                            uint32_t aBase, uint32_t bBase)
{
    int row = t>>2, ch = t&3;
    const __half* a0 = A + (size_t)(bm+row)*lda + k0 + ch*8;
    const __half* a1 = a0 + (size_t)64*lda;
    const __half* b0 = W + (size_t)(bn+row)*ldw + k0 + ch*8;
    uint32_t d0 = aBase + 4*swzw(row,    ch*4);
    uint32_t d1 = aBase + 4*swzw(row+64, ch*4);
    uint32_t db = bBase + 4*swzw(row,    ch*4);
    asm volatile("cp.async.cg.shared.global [%0], [%1], 16;\n" :: "r"(d0), "l"(a0) : "memory");
    asm volatile("cp.async.cg.shared.global [%0], [%1], 16;\n" :: "r"(d1), "l"(a1) : "memory");
    asm volatile("cp.async.cg.shared.global [%0], [%1], 16;\n" :: "r"(db), "l"(b0) : "memory");
}

__device__ __forceinline__ void ldm_x4(uint32_t& r0, uint32_t& r1, uint32_t& r2, uint32_t& r3,
                                       uint32_t addr){
    asm volatile("ldmatrix.sync.aligned.m8n8.x4.shared.b16 {%0,%1,%2,%3}, [%4];"
        : "=r"(r0), "=r"(r1), "=r"(r2), "=r"(r3) : "r"(addr));
}

__global__ void __launch_bounds__(256,3) gemm_f16(
    const __half* __restrict__ A, int lda,
    const __half* __restrict__ W, int ldw, int S,
    const float* __restrict__ b0, const float* __restrict__ b1,
    const float* __restrict__ b2, const float* __restrict__ b3,
    const float* __restrict__ e0, const float* __restrict__ e1,
    const float* __restrict__ e2, const float* __restrict__ e3,
    int has2, float* __restrict__ C, int ldc)
{
    __shared__ __align__(16) uint32_t As[3][2048];
    __shared__ __align__(16) uint32_t Bs[3][1024];
    const int tid = threadIdx.x;
    const int wid = tid>>5, lane = tid&31;
    const int bm = blockIdx.y*128, bn = blockIdx.x*64;
    const int wm = (wid>>1)*32, wn = (wid&1)*32;
    const int g = lane>>2, tig = lane&3;
    const int grp = lane>>3, rowin = lane&7;

    const uint32_t smA = (uint32_t)__cvta_generic_to_shared(&As[0][0]);
    const uint32_t smB = (uint32_t)__cvta_generic_to_shared(&Bs[0][0]);

    float acc[2][4][4];
    #pragma unroll
    for (int i=0;i<2;i++)
        #pragma unroll
        for (int j=0;j<4;j++)
            #pragma unroll
            for (int t=0;t<4;t++) acc[i][j][t]=0.f;

    issue_stage(A, lda, W, ldw, bm, bn, tid, 0, smA, smB);
    asm volatile("cp.async.commit_group;\n" ::: "memory");
    issue_stage(A, lda, W, ldw, bm, bn, tid, 32, smA + 8192, smB + 4096);
    asm volatile("cp.async.commit_group;\n" ::: "memory");

    for (int s = 0; s < S; s++){
        if (s+1 < S) asm volatile("cp.async.wait_group 1;\n" ::: "memory");
        else         asm volatile("cp.async.wait_group 0;\n" ::: "memory");
        __syncthreads();

        if (s+2 < S){
            int b2i = (s+2)%3;
            issue_stage(A, lda, W, ldw, bm, bn, tid, (s+2)*32, smA + b2i*8192, smB + b2i*4096);
            asm volatile("cp.async.commit_group;\n" ::: "memory");
        }

        const int buf = s%3;
        const uint32_t aBase = smA + buf*8192;
        const uint32_t bBase = smB + buf*4096;

        #pragma unroll
        for (int kk=0;kk<2;kk++){
            const int kb = kk*8;
            uint32_t af[2][4], bf[2][4];
            #pragma unroll
            for (int mf=0;mf<2;mf++){
                int arow  = wm + mf*16 + ((grp&1)<<3) + rowin;
                int aword = kb + ((grp>>1)<<2);
                uint32_t aw = (arow<<4) + (aword ^ (((arow>>1)&3)<<2));
                ldm_x4(af[mf][0], af[mf][1], af[mf][2], af[mf][3], aBase + 4*aw);
            }
            #pragma unroll
            for (int nf2=0;nf2<2;nf2++){
                int brow  = wn + nf2*16 + ((grp>>1)<<3) + rowin;
                int bword = kb + ((grp&1)<<2);
                uint32_t bw = (brow<<4) + (bword ^ (((brow>>1)&3)<<2));
                ldm_x4(bf[nf2][0], bf[nf2][1], bf[nf2][2], bf[nf2][3], bBase + 4*bw);
            }
            #pragma unroll
            for (int mf=0;mf<2;mf++)
                #pragma unroll
                for (int nf=0;nf<4;nf++)
                    asm volatile(
                        "mma.sync.aligned.m16n8k16.row.col.f32.f16.f16.f32 "
                        "{%0,%1,%2,%3},{%4,%5,%6,%7},{%8,%9},{%0,%1,%2,%3};"
                        : "+f"(acc[mf][nf][0]), "+f"(acc[mf][nf][1]),
                          "+f"(acc[mf][nf][2]), "+f"(acc[mf][nf][3])
                        : "r"(af[mf][0]), "r"(af[mf][1]), "r"(af[mf][2]), "r"(af[mf][3]),
                          "r"(bf[nf>>1][(nf&1)*2]), "r"(bf[nf>>1][(nf&1)*2+1]));
        }
    }

    // epilogue (bias is quartered by 1024-col blocks)
    const int q = bn>>10;
    const float* bq = (q==0)?b0:(q==1)?b1:(q==2)?b2:b3;
    const float* eq = (q==0)?e0:(q==1)?e1:(q==2)?e2:e3;
    #pragma unroll
    for (int mf=0;mf<2;mf++){
        int row = bm + wm + mf*16 + g;
        #pragma unroll
        for (int nf=0;nf<4;nf++){
            int col = bn + wn + nf*8 + 2*tig;
            int cq = col & 1023;
            float b0v = bq[cq], b1v = bq[cq+1];
            if (has2){ b0v += eq[cq]; b1v += eq[cq+1]; }
            float2 v0; v0.x = acc[mf][nf][0] + b0v; v0.y = acc[mf][nf][1] + b1v;
            float2 v1; v1.x = acc[mf][nf][2] + b0v; v1.y = acc[mf][nf][3] + b1v;
            *(float2*)&C[(size_t)row*ldc + col]     = v0;
            *(float2*)&C[(size_t)(row+8)*ldc + col] = v1;
        }
    }
}

// ---------------- LSTM pointwise (gate order i,f,g,o) ----------------------
__global__ void lstm_pw(const float* __restrict__ g, const float* __restrict__ cprev,
                        float* __restrict__ hout, float* __restrict__ cout,
                        __half* __restrict__ hout16, int ldh)
{
    int idx = blockIdx.x*blockDim.x + threadIdx.x;
    if (idx >= BSZ*CD) return;
    int bb = idx >> 10, cc = idx & 1023;
    const float* gr = g + (size_t)bb*4096;
    float gi = sigf(gr[cc]);
    float gf = sigf(gr[1024+cc]);
    float gg = tanhfast(gr[2048+cc]);
    float go = sigf(gr[3072+cc]);
    float cn = gf*cprev[idx] + gi*gg;
    cout[idx] = cn;
    float h = go * tanhfast(cn);
    hout[idx] = h;
    hout16[(size_t)bb*ldh + cc] = __float2half(h);
}

// ---------------- fused small heads -----------------------------------------
__global__ void gemv_heads4(const float* __restrict__ h,
                            const float* __restrict__ Wrb, const float* __restrict__ brb,
                            const float* __restrict__ Wwb, const float* __restrict__ bwb,
                            const float* __restrict__ Wsh, const float* __restrict__ bsh,
                            const float* __restrict__ Wga, const float* __restrict__ bga,
                            float* __restrict__ orb, float* __restrict__ owb,
                            float* __restrict__ osh, float* __restrict__ oga)
{
    int gw = (blockIdx.x*blockDim.x + threadIdx.x) >> 5;
    int lane = threadIdx.x & 31;
    if (gw >= BSZ*48) return;
    int bidx = gw / 48, t = gw - bidx*48;
    const float* W; const float* bias; float* out; int n; int nout;
    if (t < 8)       { W=Wrb; bias=brb; out=orb; n=t;     nout=8;  }
    else if (t < 16) { W=Wwb; bias=bwb; out=owb; n=t-8;   nout=8;  }
    else if (t < 40) { W=Wsh; bias=bsh; out=osh; n=t-16;  nout=24; }
    else             { W=Wga; bias=bga; out=oga; n=t-40;  nout=8;  }
    const float4* hv = (const float4*)(h + (size_t)bidx*CD);
    const float4* wv = (const float4*)(W + (size_t)n*CD);
    float s = 0.f;
    #pragma unroll 4
    for (int i=lane; i<CD/4; i+=32){
        float4 a=hv[i], w=wv[i];
        s += a.x*w.x + a.y*w.y + a.z*w.z + a.w*w.w;
    }
    #pragma unroll
    for (int o=16;o;o>>=1) s += __shfl_xor_sync(0xffffffffu, s, o);
    if (lane==0) out[(size_t)bidx*nout + n] = s + bias[n];
}

// ---------------- content addressing (write path) --------------------------
__global__ void __launch_bounds__(256) content_w(
    const float* __restrict__ Mm,
    const float* __restrict__ Kraw, int ldk,
    const float* __restrict__ braw,
    float* __restrict__ wout)
{
    int b = blockIdx.x;
    __shared__ __align__(16) float Kn[HH][DD];
    __shared__ float cosm[HH][ND];
    __shared__ float inv[HH];
    int tid = threadIdx.x, wid = tid>>5, lane = tid&31;

    for (int i=tid; i<HH*DD; i+=256) Kn[i>>7][i&127] = Kraw[(size_t)b*ldk + i];
    __syncthreads();
    {
        float s=0.f;
        for (int d=lane; d<DD; d+=32){ float v=Kn[wid][d]; s+=v*v; }
        #pragma unroll
        for (int o=16;o;o>>=1) s += __shfl_xor_sync(0xffffffffu, s, o);
        if (lane==0) inv[wid] = 1.f / fmaxf(sqrtf(s), 1e-12f);
    }
    __syncthreads();
    for (int i=tid; i<HH*DD; i+=256) Kn[i>>7][i&127] *= inv[i>>7];
    __syncthreads();

    for (int n = wid; n < ND; n += 8) {
        const float4* Mr = (const float4*)(Mm + ((size_t)b*ND + n)*DD);
        float4 mv = Mr[lane];
        float vals[9];
        vals[8] = mv.x*mv.x + mv.y*mv.y + mv.z*mv.z + mv.w*mv.w;
        #pragma unroll
        for (int h=0;h<HH;h++){
            float4 kv = *(const float4*)&Kn[h][lane*4];
            vals[h] = mv.x*kv.x + mv.y*kv.y + mv.z*kv.z + mv.w*kv.w;
        }
        #pragma unroll
        for (int o=16;o;o>>=1)
            #pragma unroll
            for (int j=0;j<9;j++) vals[j] += __shfl_xor_sync(0xffffffffu, vals[j], o);
        if (lane==0){
            float im = 1.f / fmaxf(sqrtf(vals[8]), 1e-12f);
            #pragma unroll
            for (int h=0;h<HH;h++) cosm[h][n] = vals[h]*im;
        }
    }
    __syncthreads();

    float beta = softplusf_(braw[(size_t)b*HH + wid]);
    float mx = -1e30f;
    #pragma unroll
    for (int k=0;k<8;k++) mx = fmaxf(mx, beta*cosm[wid][lane+32*k]);
    #pragma unroll
    for (int o=16;o;o>>=1) mx = fmaxf(mx, __shfl_xor_sync(0xffffffffu, mx, o));
    float ev[8]; float sum=0.f;
    #pragma unroll
    for (int k=0;k<8;k++){ float e = expf(beta*cosm[wid][lane+32*k]-mx); ev[k]=e; sum+=e; }
    #pragma unroll
    for (int o=16;o;o>>=1) sum += __shfl_xor_sync(0xffffffffu, sum, o);
    float isum = 1.f/sum;
    #pragma unroll
    for (int k=0;k<8;k++) wout[((size_t)b*HH+wid)*ND + lane+32*k] = ev[k]*isum;
}

// ---------------- memory update ---------------------------------------------
__global__ void __launch_bounds__(128) mem_update(
    const float* __restrict__ Mp, const float* __restrict__ ww,
    const float* __restrict__ eraw, const float* __restrict__ araw, int ldk,
    float* __restrict__ Mo)
{
    int b = blockIdx.x, chunk = blockIdx.y;
    int tid = threadIdx.x;
    __shared__ float er[HH][DD], ad[HH][DD], ws[HH][32];
    for (int i=tid; i<HH*DD; i+=128){
        er[i>>7][i&127] = sigf(eraw[(size_t)b*ldk + i]);
        ad[i>>7][i&127] = tanhfast(araw[(size_t)b*ldk + i]);
    }
    for (int i=tid; i<HH*32; i+=128){
        int h=i>>5, nn=i&31;
        ws[h][nn] = ww[((size_t)b*HH+h)*ND + chunk*32+nn];
    }
    __syncthreads();
    for (int nn=0; nn<32; nn++){
        int n = chunk*32+nn;
        size_t off = ((size_t)b*ND+n)*DD + tid;
        float mp = Mp[off];
        float es=0.f, as=0.f;
        #pragma unroll
        for (int h=0;h<HH;h++){ float w=ws[h][nn]; es += w*er[h][tid]; as += w*ad[h][tid]; }
        Mo[off] = mp*(1.f-es) + as;
    }
}

// ---------------- read path: content + shift + sharpen ---------------------
__global__ void __launch_bounds__(256) content_r(
    const float* __restrict__ Mm,
    const float* __restrict__ Kraw, int ldk,
    const float* __restrict__ braw,
    const float* __restrict__ shraw,
    const float* __restrict__ garaw,
    float* __restrict__ wout)
{
    int b = blockIdx.x;
    __shared__ __align__(16) float Kn[HH][DD];
    __shared__ float cosm[HH][ND];
    __shared__ float inv[HH];
    __shared__ float s3[HH][3];
    int tid = threadIdx.x, wid = tid>>5, lane = tid&31;

    for (int i=tid; i<HH*DD; i+=256) Kn[i>>7][i&127] = Kraw[(size_t)b*ldk + i];
    __syncthreads();
    {
        float s=0.f;
        for (int d=lane; d<DD; d+=32){ float v=Kn[wid][d]; s+=v*v; }
        #pragma unroll
        for (int o=16;o;o>>=1) s += __shfl_xor_sync(0xffffffffu, s, o);
        if (lane==0) inv[wid] = 1.f / fmaxf(sqrtf(s), 1e-12f);
    }
    __syncthreads();
    for (int i=tid; i<HH*DD; i+=256) Kn[i>>7][i&127] *= inv[i>>7];
    __syncthreads();

    for (int n = wid; n < ND; n += 8) {
        const float4* Mr = (const float4*)(Mm + ((size_t)b*ND + n)*DD);
        float4 mv = Mr[lane];
        float vals[9];
        vals[8] = mv.x*mv.x + mv.y*mv.y + mv.z*mv.z + mv.w*mv.w;
        #pragma unroll
        for (int h=0;h<HH;h++){
            float4 kv = *(const float4*)&Kn[h][lane*4];
            vals[h] = mv.x*kv.x + mv.y*kv.y + mv.z*kv.z + mv.w*kv.w;
        }
        #pragma unroll
        for (int o=16;o;o>>=1)
            #pragma unroll
            for (int j=0;j<9;j++) vals[j] += __shfl_xor_sync(0xffffffffu, vals[j], o);
        if (lane==0){
            float im = 1.f / fmaxf(sqrtf(vals[8]), 1e-12f);
            #pragma unroll
            for (int h=0;h<HH;h++) cosm[h][n] = vals[h]*im;
        }
    }
    __syncthreads();

    float beta = softplusf_(braw[(size_t)b*HH + wid]);
    float mx = -1e30f;
    #pragma unroll
    for (int k=0;k<8;k++) mx = fmaxf(mx, beta*cosm[wid][lane+32*k]);
    #pragma unroll
    for (int o=16;o;o>>=1) mx = fmaxf(mx, __shfl_xor_sync(0xffffffffu, mx, o));
    float ev[8]; float sum=0.f;
    #pragma unroll
    for (int k=0;k<8;k++){ float e = expf(beta*cosm[wid][lane+32*k]-mx); ev[k]=e; sum+=e; }
    #pragma unroll
    for (int o=16;o;o>>=1) sum += __shfl_xor_sync(0xffffffffu, sum, o);
    float isum = 1.f/sum;
    __syncthreads();
    #pragma unroll
    for (int k=0;k<8;k++) cosm[wid][lane+32*k] = ev[k]*isum;

    if (lane==0){
        const float* sr = shraw + ((size_t)b*HH + wid)*3;
        float a=sr[0], bb2=sr[1], cc=sr[2];
        float m = fmaxf(a, fmaxf(bb2, cc));
        float ea=expf(a-m), eb=expf(bb2-m), ec=expf(cc-m);
        float is = 1.f/(ea+eb+ec);
        s3[wid][0]=ea*is; s3[wid][1]=eb*is; s3[wid][2]=ec*is;
    }
    __syncthreads();

    float sh0 = s3[wid][0], sh1 = s3[wid][1], sh2 = s3[wid][2];
    float gexp = 1.f + softplusf_(garaw[(size_t)b*HH + wid]);
    float wg[8]; float sum2=0.f;
    #pragma unroll
    for (int k=0;k<8;k++){
        int n = lane+32*k;
        float wsv = sh0*cosm[wid][(n+1)&255] + sh1*cosm[wid][n] + sh2*cosm[wid][(n-1)&255];
        float p = powf(wsv, gexp);
        wg[k]=p; sum2+=p;
    }
    #pragma unroll
    for (int o=16;o;o>>=1) sum2 += __shfl_xor_sync(0xffffffffu, sum2, o);
    float inv2 = 1.f/(sum2+1e-12f);
    #pragma unroll
    for (int k=0;k<8;k++) wout[((size_t)b*HH+wid)*ND + lane+32*k] = wg[k]*inv2;
}

// ---------------- r = w_r @ M ----------------------------------------------
__global__ void __launch_bounds__(128) read_r(
    const float* __restrict__ Mm, const float* __restrict__ wr, float* __restrict__ r)
{
    int b = blockIdx.x;
    int d = threadIdx.x;
    __shared__ float ws[HH][ND];
    for (int i=d; i<HH*ND; i+=128) ws[i>>8][i&255] = wr[(size_t)b*HH*ND + i];
    __syncthreads();
    float acc[HH];
    #pragma unroll
    for (int h=0;h<HH;h++) acc[h]=0.f;
    for (int n=0; n<ND; n++){
        float m = Mm[((size_t)b*ND+n)*DD + d];
        #pragma unroll
        for (int h=0;h<HH;h++) acc[h] += ws[h][n]*m;
    }
    #pragma unroll
    for (int h=0;h<HH;h++) r[((size_t)b*HH+h)*DD + d] = acc[h];
}

// ---------------- launcher ---------------------------------------------------
extern "C" void kernel_launch(void* const* d_in, const int* in_sizes, int n_in,
                              void* d_out, int out_size)
{
    const float* x      = (const float*)d_in[0];
    const float* h1     = (const float*)d_in[1];
    const float* c1     = (const float*)d_in[2];
    const float* h2     = (const float*)d_in[3];
    const float* c2     = (const float*)d_in[4];
    const float* r_prev = (const float*)d_in[6];
    const float* M_prev = (const float*)d_in[7];
    const float* W_ih1  = (const float*)d_in[8];
    const float* W_hh1  = (const float*)d_in[9];
    const float* b_ih1  = (const float*)d_in[10];
    const float* b_hh1  = (const float*)d_in[11];
    const float* W_ih2  = (const float*)d_in[12];
    const float* W_hh2  = (const float*)d_in[13];
    const float* b_ih2  = (const float*)d_in[14];
    const float* b_hh2  = (const float*)d_in[15];
    const float* W_rk   = (const float*)d_in[16];
    const float* b_rk   = (const float*)d_in[17];
    const float* W_wk   = (const float*)d_in[18];
    const float* b_wk   = (const float*)d_in[19];
    const float* W_rb   = (const float*)d_in[20];
    const float* b_rb   = (const float*)d_in[21];
    const float* W_wb   = (const float*)d_in[22];
    const float* b_wb   = (const float*)d_in[23];
    const float* W_er   = (const float*)d_in[24];
    const float* b_er   = (const float*)d_in[25];
    const float* W_ad   = (const float*)d_in[26];
    const float* b_ad   = (const float*)d_in[27];
    const float* W_sh   = (const float*)d_in[28];
    const float* b_sh   = (const float*)d_in[29];
    const float* W_ga   = (const float*)d_in[30];
    const float* b_ga   = (const float*)d_in[31];

    float* out = (float*)d_out;
    const size_t HC = (size_t)BSZ*CD;
    float* h1n = out;
    float* c1n = out + HC;
    float* h2n = out + 2*HC;
    float* c2n = out + 3*HC;
    float* wr  = out + 4*HC;
    float* rr  = wr + (size_t)BSZ*HH*ND;
    float* Mo  = rr + (size_t)BSZ*HH*DD;

    float* S = nullptr;
    cudaGetSymbolAddress((void**)&S, g_scratch);
    float* gates = S + GATES_OFF;
    float* heads = S + HEADS_OFF;
    float* WW    = S + WW_OFF;
    float* BR    = S + BR_OFF;
    float* BW    = S + BW_OFF;
    float* SHm   = S + SH_OFF;
    float* GA    = S + GA_OFF;
    __half* Hh   = (__half*)(S + FP16_OFF);

    // 0) batched f32->f16 conversion + concat gather
    {
        CvtCfg c{};
        //                 src     dst-base          n8      cpr  drc  doff
        struct Row { const float* s; unsigned d; int n8, cpr, drc, doff; };
        const Row rows[13] = {
            { W_ih1, WCAT1_H,            786432, 192, 320, 0   },
            { W_hh1, WCAT1_H,            524288, 128, 320, 192 },
            { W_ih2, WCAT2_H,            524288, 128, 256, 0   },
            { W_hh2, WCAT2_H,            524288, 128, 256, 128 },
            { W_rk,  WHD_H,              131072, 128, 128, 0   },
            { W_wk,  WHD_H + 1048576u,   131072, 128, 128, 0   },
            { W_er,  WHD_H + 2097152u,   131072, 128, 128, 0   },
            { W_ad,  WHD_H + 3145728u,   131072, 128, 128, 0   },
            { x,     ACAT1_H,             32768,  64, 320, 0   },
            { r_prev,ACAT1_H,             65536, 128, 320, 64  },
            { h1,    ACAT1_H,             65536, 128, 320, 192 },
            { h2,    ACAT2_H,             65536, 128, 256, 128 },
            { M_prev,ACAT2_H,                 0, 128, 128, 0   }, // unused pad
        };
        int acc = 0;
        for (int i=0;i<13;i++){
            c.s[i].src = rows[i].s;
            c.s[i].dst = Hh + rows[i].d;
            c.s[i].cpr = rows[i].cpr;
            c.s[i].drc = rows[i].drc;
            c.s[i].doff = rows[i].doff;
            c.off[i] = acc;
            acc += rows[i].n8;
        }
        c.off[13] = acc;
        c.total8 = acc;
        cvt_f2h<<<(c.total8 + 255)/256, 256>>>(c);
    }

    dim3 ggrid(4096/64, BSZ/128);   // 256 CTAs

    // 1) LSTM1: gates = Acat1 @ Wcat1^T + b_ih1 + b_hh1
    gemm_f16<<<ggrid, 256>>>(Hh+ACAT1_H, 2560, Hh+WCAT1_H, 2560, 2560/32,
        b_ih1, b_ih1+1024, b_ih1+2048, b_ih1+3072,
        b_hh1, b_hh1+1024, b_hh1+2048, b_hh1+3072,
        1, gates, 4096);
    lstm_pw<<<(BSZ*CD + 255)/256, 256>>>(gates, c1, h1n, c1n, Hh+ACAT2_H, 2048);

    // 2) LSTM2: gates = Acat2 @ Wcat2^T + b_ih2 + b_hh2
    gemm_f16<<<ggrid, 256>>>(Hh+ACAT2_H, 2048, Hh+WCAT2_H, 2048, 2048/32,
        b_ih2, b_ih2+1024, b_ih2+2048, b_ih2+3072,
        b_hh2, b_hh2+1024, b_hh2+2048, b_hh2+3072,
        1, gates, 4096);
    lstm_pw<<<(BSZ*CD + 255)/256, 256>>>(gates, c2, h2n, c2n, Hh+H2NH, 1024);

    // 3) fused head projections: heads = RK|WK|ER|AD
    gemm_f16<<<ggrid, 256>>>(Hh+H2NH, 1024, Hh+WHD_H, 1024, 1024/32,
        b_rk, b_wk, b_er, b_ad,
        nullptr, nullptr, nullptr, nullptr,
        0, heads, 4096);

    // 4) fused small heads (raw pre-activation)
    gemv_heads4<<<(BSZ*48*32 + 255)/256, 256>>>(h2n,
        W_rb, b_rb, W_wb, b_wb, W_sh, b_sh, W_ga, b_ga,
        BR, BW, SHm, GA);

    // 5) write-path content weights on M_prev (WK at heads+1024)
    content_w<<<BSZ, 256>>>(M_prev, heads + 1024, 4096, BW, WW);

    // 6) memory update -> Mo (ER at heads+2048, AD at heads+3072)
    mem_update<<<dim3(BSZ, 8), 128>>>(M_prev, WW, heads + 2048, heads + 3072, 4096, Mo);

    // 7) read-path (RK at heads+0)
    content_r<<<BSZ, 256>>>(Mo, heads, 4096, BR, SHm, GA, wr);

    // 8) r = w_r @ M
    read_r<<<BSZ, 128>>>(Mo, wr, rr);
}